// round 2
// baseline (speedup 1.0000x reference)
#include <cuda_runtime.h>
#include <math.h>

// Problem constants (fixed by setup_inputs)
#define BSZ   2
#define LSEQ  2048
#define DM    1024
#define DI    2048          // d_inner
#define DS    16            // d_state
#define DTR   64            // dt_rank
#define NX    96            // dt_rank + 2*d_state
#define MROWS (BSZ*LSEQ)    // 4096
#define E2    (2*DI)        // 4096

// -------- scratch (device globals; no allocation allowed) --------
__device__ float g_xz  [(size_t)MROWS * E2];   // in_proj output (xi | z)
__device__ float g_xc  [(size_t)MROWS * DI];   // conv+silu output
__device__ float g_xdbl[(size_t)MROWS * NX];   // x_proj output (dt_r | B | C)
__device__ float g_dt  [(size_t)MROWS * DI];   // softplus(dt)
__device__ float g_yact[(size_t)MROWS * DI];   // scan out * silu(z)
__device__ float g_yout[(size_t)MROWS * DM];   // out_proj output

// ---------------------------------------------------------------
// Generic fp32 GEMM: C[M,N] = A[M,K] * B[N,K]^T  (both K-major)
// 64x64 tile, 256 threads, 4x4 micro-tile, K-tile 16.
// M must be a multiple of 64 (always 4096 here); N,K checked.
// EPI==1: v = softplus(v + bias[n])
// ---------------------------------------------------------------
template<int EPI>
__global__ void __launch_bounds__(256) sgemm_abt(
    const float* __restrict__ A, int lda,
    const float* __restrict__ Bm, int ldb,
    float* __restrict__ C, int ldc,
    int N, int K, const float* __restrict__ bias)
{
    __shared__ float As[16][68];   // 68 stride: keeps float4 alignment, cuts store conflicts
    __shared__ float Bs[16][68];

    const int tid = threadIdx.x;
    const int tx  = tid & 15;
    const int ty  = tid >> 4;
    const int m0  = blockIdx.y * 64;
    const int n0  = blockIdx.x * 64;

    const int lr = tid >> 2;        // 0..63 tile row for loads
    const int lk = (tid & 3) * 4;   // 0,4,8,12 k offset for loads

    float acc[4][4];
#pragma unroll
    for (int i = 0; i < 4; i++)
#pragma unroll
        for (int j = 0; j < 4; j++) acc[i][j] = 0.f;

    for (int k0 = 0; k0 < K; k0 += 16) {
        float4 av = *reinterpret_cast<const float4*>(
            A + (size_t)(m0 + lr) * lda + (k0 + lk));
        As[lk+0][lr] = av.x; As[lk+1][lr] = av.y;
        As[lk+2][lr] = av.z; As[lk+3][lr] = av.w;

        float4 bv = make_float4(0.f, 0.f, 0.f, 0.f);
        if (n0 + lr < N)
            bv = *reinterpret_cast<const float4*>(
                Bm + (size_t)(n0 + lr) * ldb + (k0 + lk));
        Bs[lk+0][lr] = bv.x; Bs[lk+1][lr] = bv.y;
        Bs[lk+2][lr] = bv.z; Bs[lk+3][lr] = bv.w;

        __syncthreads();
#pragma unroll
        for (int k = 0; k < 16; k++) {
            float4 a4 = *reinterpret_cast<const float4*>(&As[k][ty * 4]);
            float4 b4 = *reinterpret_cast<const float4*>(&Bs[k][tx * 4]);
            float a[4] = {a4.x, a4.y, a4.z, a4.w};
            float b[4] = {b4.x, b4.y, b4.z, b4.w};
#pragma unroll
            for (int i = 0; i < 4; i++)
#pragma unroll
                for (int j = 0; j < 4; j++)
                    acc[i][j] = fmaf(a[i], b[j], acc[i][j]);
        }
        __syncthreads();
    }

#pragma unroll
    for (int i = 0; i < 4; i++) {
        const int m = m0 + ty * 4 + i;
#pragma unroll
        for (int j = 0; j < 4; j++) {
            const int n = n0 + tx * 4 + j;
            if (n < N) {
                float v = acc[i][j];
                if (EPI == 1) {
                    v += bias[n];
                    v = (v > 20.f) ? v : log1pf(__expf(v));
                }
                C[(size_t)m * ldc + n] = v;
            }
        }
    }
}

// ---------------------------------------------------------------
// Causal depthwise conv (width 4) + bias + SiLU on xi half of xz
// ---------------------------------------------------------------
__global__ void __launch_bounds__(256) conv_silu_k(
    const float* __restrict__ cw, const float* __restrict__ cb)
{
    const int idx = blockIdx.x * 256 + threadIdx.x;   // over MROWS*DI
    const int d = idx & (DI - 1);
    const int m = idx >> 11;          // b*L + l
    const int l = m & (LSEQ - 1);

    float acc = cb[d];
#pragma unroll
    for (int j = 0; j < 4; j++) {
        const int ll = l - 3 + j;
        if (ll >= 0)
            acc = fmaf(cw[d * 4 + j], g_xz[(size_t)(m - 3 + j) * E2 + d], acc);
    }
    const float sg = 1.f / (1.f + __expf(-acc));
    g_xc[idx] = acc * sg;
}

// ---------------------------------------------------------------
// Selective scan. One thread per (b, d, s). 256 threads = 16 d x 16 s.
// Fused epilogue: y = (scan + D*u) * silu(z)
// ---------------------------------------------------------------
__global__ void __launch_bounds__(256) scan_k(
    const float* __restrict__ A_log, const float* __restrict__ Dp)
{
    const int s  = threadIdx.x & 15;
    const int dl = threadIdx.x >> 4;
    const int d  = blockIdx.x * 16 + dl;
    const int b  = blockIdx.y;

    const float As = -__expf(A_log[d * DS + s]);
    const float Dd = Dp[d];

    const float* dt_p = g_dt   + (size_t)b * LSEQ * DI + d;
    const float* u_p  = g_xc   + (size_t)b * LSEQ * DI + d;
    const float* bc_p = g_xdbl + (size_t)b * LSEQ * NX;
    const float* z_p  = g_xz   + (size_t)b * LSEQ * E2 + DI + d;
    float*       y_p  = g_yact + (size_t)b * LSEQ * DI + d;

    float h = 0.f;
    for (int l = 0; l < LSEQ; l++) {
        const float dt = __ldg(dt_p + (size_t)l * DI);
        const float u  = __ldg(u_p  + (size_t)l * DI);
        const float Bv = __ldg(bc_p + l * NX + DTR + s);
        const float Cv = __ldg(bc_p + l * NX + DTR + DS + s);

        const float dA = __expf(dt * As);
        h = fmaf(dA, h, dt * u * Bv);

        float y = h * Cv;
        y += __shfl_xor_sync(0xffffffffu, y, 8);
        y += __shfl_xor_sync(0xffffffffu, y, 4);
        y += __shfl_xor_sync(0xffffffffu, y, 2);
        y += __shfl_xor_sync(0xffffffffu, y, 1);

        if (s == 0) {
            const float zv = __ldg(z_p + (size_t)l * E2);
            const float sg = 1.f / (1.f + __expf(-zv));
            y_p[(size_t)l * DI] = (y + Dd * u) * (zv * sg);
        }
    }
}

// ---------------------------------------------------------------
// Residual add + LayerNorm. One block per row of 1024.
// ---------------------------------------------------------------
__global__ void __launch_bounds__(256) ln_k(
    const float* __restrict__ x,
    const float* __restrict__ g, const float* __restrict__ bb,
    float* __restrict__ out)
{
    const int r = blockIdx.x;
    const float* yp = g_yout + (size_t)r * DM;
    const float* xp = x      + (size_t)r * DM;

    float v[4];
    float sum = 0.f, sq = 0.f;
#pragma unroll
    for (int k = 0; k < 4; k++) {
        const int c = threadIdx.x + k * 256;
        const float t = yp[c] + xp[c];
        v[k] = t; sum += t; sq += t * t;
    }

    __shared__ float ssum[8], ssq[8];
#pragma unroll
    for (int o = 16; o; o >>= 1) {
        sum += __shfl_xor_sync(0xffffffffu, sum, o);
        sq  += __shfl_xor_sync(0xffffffffu, sq,  o);
    }
    const int w = threadIdx.x >> 5;
    if ((threadIdx.x & 31) == 0) { ssum[w] = sum; ssq[w] = sq; }
    __syncthreads();

    float ts = 0.f, tq = 0.f;
#pragma unroll
    for (int i = 0; i < 8; i++) { ts += ssum[i]; tq += ssq[i]; }

    const float mu  = ts * (1.f / DM);
    const float var = tq * (1.f / DM) - mu * mu;
    const float inv = rsqrtf(var + 1e-5f);

#pragma unroll
    for (int k = 0; k < 4; k++) {
        const int c = threadIdx.x + k * 256;
        out[(size_t)r * DM + c] = (v[k] - mu) * inv * g[c] + bb[c];
    }
}

// ---------------------------------------------------------------
extern "C" void kernel_launch(void* const* d_in, const int* in_sizes, int n_in,
                              void* d_out, int out_size)
{
    const float* x          = (const float*)d_in[0];
    const float* in_proj_w  = (const float*)d_in[1];
    const float* conv_w     = (const float*)d_in[2];
    const float* conv_b     = (const float*)d_in[3];
    const float* x_proj_w   = (const float*)d_in[4];
    const float* dt_proj_w  = (const float*)d_in[5];
    const float* dt_proj_b  = (const float*)d_in[6];
    const float* A_log      = (const float*)d_in[7];
    const float* Dp         = (const float*)d_in[8];
    const float* out_proj_w = (const float*)d_in[9];
    const float* ln_g       = (const float*)d_in[10];
    const float* ln_b       = (const float*)d_in[11];
    float* out = (float*)d_out;

    float *xz, *xc, *xdbl, *dt, *yact, *yout;
    cudaGetSymbolAddress((void**)&xz,   g_xz);
    cudaGetSymbolAddress((void**)&xc,   g_xc);
    cudaGetSymbolAddress((void**)&xdbl, g_xdbl);
    cudaGetSymbolAddress((void**)&dt,   g_dt);
    cudaGetSymbolAddress((void**)&yact, g_yact);
    cudaGetSymbolAddress((void**)&yout, g_yout);

    // 1) xz = x @ in_proj_w^T       (4096 x 4096 x 1024)
    sgemm_abt<0><<<dim3(E2 / 64, MROWS / 64), 256>>>(
        x, DM, in_proj_w, DM, xz, E2, E2, DM, nullptr);

    // 2) xc = silu(causal_conv(xi) + conv_b)
    conv_silu_k<<<(MROWS * DI) / 256, 256>>>(conv_w, conv_b);

    // 3) x_dbl = xc @ x_proj_w^T    (4096 x 96 x 2048)
    sgemm_abt<0><<<dim3((NX + 63) / 64, MROWS / 64), 256>>>(
        xc, DI, x_proj_w, DI, xdbl, NX, NX, DI, nullptr);

    // 4) dt = softplus(dt_r @ dt_proj_w^T + b)  (4096 x 2048 x 64)
    sgemm_abt<1><<<dim3(DI / 64, MROWS / 64), 256>>>(
        xdbl, NX, dt_proj_w, DTR, dt, DI, DI, DTR, dt_proj_b);

    // 5) selective scan + gating
    scan_k<<<dim3(DI / 16, BSZ), 256>>>(A_log, Dp);

    // 6) yout = yact @ out_proj_w^T (4096 x 1024 x 2048)
    sgemm_abt<0><<<dim3(DM / 64, MROWS / 64), 256>>>(
        yact, DI, out_proj_w, DI, yout, DM, DM, DI, nullptr);

    // 7) out = layernorm(yout + x)
    ln_k<<<MROWS, 256>>>(x, ln_g, ln_b, out);
}

// round 5
// speedup vs baseline: 1.0107x; 1.0107x over previous
#include <cuda_runtime.h>
#include <math.h>

// Problem constants (fixed by setup_inputs)
#define BSZ   2
#define LSEQ  2048
#define DM    1024
#define DI    2048          // d_inner
#define DS    16            // d_state
#define DTR   64            // dt_rank
#define NX    96            // dt_rank + 2*d_state
#define MROWS (BSZ*LSEQ)    // 4096
#define E2    (2*DI)        // 4096

// -------- scratch (device globals; no allocation allowed) --------
__device__ float g_xz  [(size_t)MROWS * E2];   // in_proj output (xi | z)
__device__ float g_xc  [(size_t)MROWS * DI];   // conv+silu output
__device__ float g_xdbl[(size_t)MROWS * NX];   // x_proj output (dt_r | B | C)
__device__ float g_dt  [(size_t)MROWS * DI];   // softplus(dt)
__device__ float g_yact[(size_t)MROWS * DI];   // scan out * silu(z)
__device__ float g_yout[(size_t)MROWS * DM];   // out_proj output

// ---------------------------------------------------------------
// Generic fp32 GEMM: C[M,N] = A[M,K] * B[N,K]^T  (both K-major)
// 64x64 tile, 256 threads, 4x4 micro-tile, K-tile 16.
// M must be a multiple of 64 (always 4096 here); N,K checked.
// EPI==1: v = softplus(v + bias[n])
// ---------------------------------------------------------------
template<int EPI>
__global__ void __launch_bounds__(256) sgemm_abt(
    const float* __restrict__ A, int lda,
    const float* __restrict__ Bm, int ldb,
    float* __restrict__ C, int ldc,
    int N, int K, const float* __restrict__ bias)
{
    __shared__ float As[16][68];   // 68 stride: keeps float4 alignment, cuts store conflicts
    __shared__ float Bs[16][68];

    const int tid = threadIdx.x;
    const int tx  = tid & 15;
    const int ty  = tid >> 4;
    const int m0  = blockIdx.y * 64;
    const int n0  = blockIdx.x * 64;

    const int lr = tid >> 2;        // 0..63 tile row for loads
    const int lk = (tid & 3) * 4;   // 0,4,8,12 k offset for loads

    float acc[4][4];
#pragma unroll
    for (int i = 0; i < 4; i++)
#pragma unroll
        for (int j = 0; j < 4; j++) acc[i][j] = 0.f;

    for (int k0 = 0; k0 < K; k0 += 16) {
        float4 av = *reinterpret_cast<const float4*>(
            A + (size_t)(m0 + lr) * lda + (k0 + lk));
        As[lk+0][lr] = av.x; As[lk+1][lr] = av.y;
        As[lk+2][lr] = av.z; As[lk+3][lr] = av.w;

        float4 bv = make_float4(0.f, 0.f, 0.f, 0.f);
        if (n0 + lr < N)
            bv = *reinterpret_cast<const float4*>(
                Bm + (size_t)(n0 + lr) * ldb + (k0 + lk));
        Bs[lk+0][lr] = bv.x; Bs[lk+1][lr] = bv.y;
        Bs[lk+2][lr] = bv.z; Bs[lk+3][lr] = bv.w;

        __syncthreads();
#pragma unroll
        for (int k = 0; k < 16; k++) {
            float4 a4 = *reinterpret_cast<const float4*>(&As[k][ty * 4]);
            float4 b4 = *reinterpret_cast<const float4*>(&Bs[k][tx * 4]);
            float a[4] = {a4.x, a4.y, a4.z, a4.w};
            float b[4] = {b4.x, b4.y, b4.z, b4.w};
#pragma unroll
            for (int i = 0; i < 4; i++)
#pragma unroll
                for (int j = 0; j < 4; j++)
                    acc[i][j] = fmaf(a[i], b[j], acc[i][j]);
        }
        __syncthreads();
    }

#pragma unroll
    for (int i = 0; i < 4; i++) {
        const int m = m0 + ty * 4 + i;
#pragma unroll
        for (int j = 0; j < 4; j++) {
            const int n = n0 + tx * 4 + j;
            if (n < N) {
                float v = acc[i][j];
                if (EPI == 1) {
                    v += bias[n];
                    v = (v > 20.f) ? v : log1pf(__expf(v));
                }
                C[(size_t)m * ldc + n] = v;
            }
        }
    }
}

// ---------------------------------------------------------------
// Causal depthwise conv (width 4) + bias + SiLU on xi half of xz
// ---------------------------------------------------------------
__global__ void __launch_bounds__(256) conv_silu_k(
    const float* __restrict__ cw, const float* __restrict__ cb)
{
    const int idx = blockIdx.x * 256 + threadIdx.x;   // over MROWS*DI
    const int d = idx & (DI - 1);
    const int m = idx >> 11;          // b*L + l
    const int l = m & (LSEQ - 1);

    float acc = cb[d];
#pragma unroll
    for (int j = 0; j < 4; j++) {
        const int ll = l - 3 + j;
        if (ll >= 0)
            acc = fmaf(cw[d * 4 + j], g_xz[(size_t)(m - 3 + j) * E2 + d], acc);
    }
    const float sg = 1.f / (1.f + __expf(-acc));
    g_xc[idx] = acc * sg;
}

// ---------------------------------------------------------------
// Selective scan. One thread per (b, d, s). 256 threads = 16 d x 16 s.
// Fused epilogue: y = (scan + D*u) * silu(z)
// ---------------------------------------------------------------
__global__ void __launch_bounds__(256) scan_k(
    const float* __restrict__ A_log, const float* __restrict__ Dp)
{
    const int s  = threadIdx.x & 15;
    const int dl = threadIdx.x >> 4;
    const int d  = blockIdx.x * 16 + dl;
    const int b  = blockIdx.y;

    const float As = -__expf(A_log[d * DS + s]);
    const float Dd = Dp[d];

    const float* dt_p = g_dt   + (size_t)b * LSEQ * DI + d;
    const float* u_p  = g_xc   + (size_t)b * LSEQ * DI + d;
    const float* bc_p = g_xdbl + (size_t)b * LSEQ * NX;
    const float* z_p  = g_xz   + (size_t)b * LSEQ * E2 + DI + d;
    float*       y_p  = g_yact + (size_t)b * LSEQ * DI + d;

    float h = 0.f;
    for (int l = 0; l < LSEQ; l++) {
        const float dt = __ldg(dt_p + (size_t)l * DI);
        const float u  = __ldg(u_p  + (size_t)l * DI);
        const float Bv = __ldg(bc_p + l * NX + DTR + s);
        const float Cv = __ldg(bc_p + l * NX + DTR + DS + s);

        const float dA = __expf(dt * As);
        h = fmaf(dA, h, dt * u * Bv);

        float y = h * Cv;
        y += __shfl_xor_sync(0xffffffffu, y, 8);
        y += __shfl_xor_sync(0xffffffffu, y, 4);
        y += __shfl_xor_sync(0xffffffffu, y, 2);
        y += __shfl_xor_sync(0xffffffffu, y, 1);

        if (s == 0) {
            const float zv = __ldg(z_p + (size_t)l * E2);
            const float sg = 1.f / (1.f + __expf(-zv));
            y_p[(size_t)l * DI] = (y + Dd * u) * (zv * sg);
        }
    }
}

// ---------------------------------------------------------------
// Residual add + LayerNorm. One block per row of 1024.
// ---------------------------------------------------------------
__global__ void __launch_bounds__(256) ln_k(
    const float* __restrict__ x,
    const float* __restrict__ g, const float* __restrict__ bb,
    float* __restrict__ out)
{
    const int r = blockIdx.x;
    const float* yp = g_yout + (size_t)r * DM;
    const float* xp = x      + (size_t)r * DM;

    float v[4];
    float sum = 0.f, sq = 0.f;
#pragma unroll
    for (int k = 0; k < 4; k++) {
        const int c = threadIdx.x + k * 256;
        const float t = yp[c] + xp[c];
        v[k] = t; sum += t; sq += t * t;
    }

    __shared__ float ssum[8], ssq[8];
#pragma unroll
    for (int o = 16; o; o >>= 1) {
        sum += __shfl_xor_sync(0xffffffffu, sum, o);
        sq  += __shfl_xor_sync(0xffffffffu, sq,  o);
    }
    const int w = threadIdx.x >> 5;
    if ((threadIdx.x & 31) == 0) { ssum[w] = sum; ssq[w] = sq; }
    __syncthreads();

    float ts = 0.f, tq = 0.f;
#pragma unroll
    for (int i = 0; i < 8; i++) { ts += ssum[i]; tq += ssq[i]; }

    const float mu  = ts * (1.f / DM);
    const float var = tq * (1.f / DM) - mu * mu;
    const float inv = rsqrtf(var + 1e-5f);

#pragma unroll
    for (int k = 0; k < 4; k++) {
        const int c = threadIdx.x + k * 256;
        out[(size_t)r * DM + c] = (v[k] - mu) * inv * g[c] + bb[c];
    }
}

// ---------------------------------------------------------------
extern "C" void kernel_launch(void* const* d_in, const int* in_sizes, int n_in,
                              void* d_out, int out_size)
{
    const float* x          = (const float*)d_in[0];
    const float* in_proj_w  = (const float*)d_in[1];
    const float* conv_w     = (const float*)d_in[2];
    const float* conv_b     = (const float*)d_in[3];
    const float* x_proj_w   = (const float*)d_in[4];
    const float* dt_proj_w  = (const float*)d_in[5];
    const float* dt_proj_b  = (const float*)d_in[6];
    const float* A_log      = (const float*)d_in[7];
    const float* Dp         = (const float*)d_in[8];
    const float* out_proj_w = (const float*)d_in[9];
    const float* ln_g       = (const float*)d_in[10];
    const float* ln_b       = (const float*)d_in[11];
    float* out = (float*)d_out;

    float *xz, *xc, *xdbl, *dt, *yact, *yout;
    cudaGetSymbolAddress((void**)&xz,   g_xz);
    cudaGetSymbolAddress((void**)&xc,   g_xc);
    cudaGetSymbolAddress((void**)&xdbl, g_xdbl);
    cudaGetSymbolAddress((void**)&dt,   g_dt);
    cudaGetSymbolAddress((void**)&yact, g_yact);
    cudaGetSymbolAddress((void**)&yout, g_yout);

    // 1) xz = x @ in_proj_w^T       (4096 x 4096 x 1024)
    sgemm_abt<0><<<dim3(E2 / 64, MROWS / 64), 256>>>(
        x, DM, in_proj_w, DM, xz, E2, E2, DM, nullptr);

    // 2) xc = silu(causal_conv(xi) + conv_b)
    conv_silu_k<<<(MROWS * DI) / 256, 256>>>(conv_w, conv_b);

    // 3) x_dbl = xc @ x_proj_w^T    (4096 x 96 x 2048)
    sgemm_abt<0><<<dim3((NX + 63) / 64, MROWS / 64), 256>>>(
        xc, DI, x_proj_w, DI, xdbl, NX, NX, DI, nullptr);

    // 4) dt = softplus(dt_r @ dt_proj_w^T + b)  (4096 x 2048 x 64)
    sgemm_abt<1><<<dim3(DI / 64, MROWS / 64), 256>>>(
        xdbl, NX, dt_proj_w, DTR, dt, DI, DI, DTR, dt_proj_b);

    // 5) selective scan + gating
    scan_k<<<dim3(DI / 16, BSZ), 256>>>(A_log, Dp);

    // 6) yout = yact @ out_proj_w^T (4096 x 1024 x 2048)
    sgemm_abt<0><<<dim3(DM / 64, MROWS / 64), 256>>>(
        yact, DI, out_proj_w, DI, yout, DM, DM, DI, nullptr);

    // 7) out = layernorm(yout + x)
    ln_k<<<MROWS, 256>>>(x, ln_g, ln_b, out);
}

// round 7
// speedup vs baseline: 1.0149x; 1.0042x over previous
#include <cuda_runtime.h>
#include <math.h>

// Problem constants (fixed by setup_inputs)
#define BSZ   2
#define LSEQ  2048
#define DM    1024
#define DI    2048          // d_inner
#define DS    16            // d_state
#define DTR   64            // dt_rank
#define NX    96            // dt_rank + 2*d_state
#define MROWS (BSZ*LSEQ)    // 4096
#define E2    (2*DI)        // 4096

// -------- scratch (device globals; no allocation allowed) --------
__device__ float g_xz  [(size_t)MROWS * E2];   // in_proj output (xi | z)
__device__ float g_xc  [(size_t)MROWS * DI];   // conv+silu output
__device__ float g_xdbl[(size_t)MROWS * NX];   // x_proj output (dt_r | B | C)
__device__ float g_dt  [(size_t)MROWS * DI];   // softplus(dt)
__device__ float g_yact[(size_t)MROWS * DI];   // scan out * silu(z)
__device__ float g_yout[(size_t)MROWS * DM];   // out_proj output

// ---------------------------------------------------------------
// Generic fp32 GEMM: C[M,N] = A[M,K] * B[N,K]^T  (both K-major)
// 64x64 tile, 256 threads, 4x4 micro-tile, K-tile 16.
// M must be a multiple of 64 (always 4096 here); N,K checked.
// EPI==1: v = softplus(v + bias[n])
// ---------------------------------------------------------------
template<int EPI>
__global__ void __launch_bounds__(256) sgemm_abt(
    const float* __restrict__ A, int lda,
    const float* __restrict__ Bm, int ldb,
    float* __restrict__ C, int ldc,
    int N, int K, const float* __restrict__ bias)
{
    __shared__ float As[16][68];   // 68 stride: keeps float4 alignment, cuts store conflicts
    __shared__ float Bs[16][68];

    const int tid = threadIdx.x;
    const int tx  = tid & 15;
    const int ty  = tid >> 4;
    const int m0  = blockIdx.y * 64;
    const int n0  = blockIdx.x * 64;

    const int lr = tid >> 2;        // 0..63 tile row for loads
    const int lk = (tid & 3) * 4;   // 0,4,8,12 k offset for loads

    float acc[4][4];
#pragma unroll
    for (int i = 0; i < 4; i++)
#pragma unroll
        for (int j = 0; j < 4; j++) acc[i][j] = 0.f;

    for (int k0 = 0; k0 < K; k0 += 16) {
        float4 av = *reinterpret_cast<const float4*>(
            A + (size_t)(m0 + lr) * lda + (k0 + lk));
        As[lk+0][lr] = av.x; As[lk+1][lr] = av.y;
        As[lk+2][lr] = av.z; As[lk+3][lr] = av.w;

        float4 bv = make_float4(0.f, 0.f, 0.f, 0.f);
        if (n0 + lr < N)
            bv = *reinterpret_cast<const float4*>(
                Bm + (size_t)(n0 + lr) * ldb + (k0 + lk));
        Bs[lk+0][lr] = bv.x; Bs[lk+1][lr] = bv.y;
        Bs[lk+2][lr] = bv.z; Bs[lk+3][lr] = bv.w;

        __syncthreads();
#pragma unroll
        for (int k = 0; k < 16; k++) {
            float4 a4 = *reinterpret_cast<const float4*>(&As[k][ty * 4]);
            float4 b4 = *reinterpret_cast<const float4*>(&Bs[k][tx * 4]);
            float a[4] = {a4.x, a4.y, a4.z, a4.w};
            float b[4] = {b4.x, b4.y, b4.z, b4.w};
#pragma unroll
            for (int i = 0; i < 4; i++)
#pragma unroll
                for (int j = 0; j < 4; j++)
                    acc[i][j] = fmaf(a[i], b[j], acc[i][j]);
        }
        __syncthreads();
    }

#pragma unroll
    for (int i = 0; i < 4; i++) {
        const int m = m0 + ty * 4 + i;
#pragma unroll
        for (int j = 0; j < 4; j++) {
            const int n = n0 + tx * 4 + j;
            if (n < N) {
                float v = acc[i][j];
                if (EPI == 1) {
                    v += bias[n];
                    v = (v > 20.f) ? v : log1pf(__expf(v));
                }
                C[(size_t)m * ldc + n] = v;
            }
        }
    }
}

// ---------------------------------------------------------------
// Causal depthwise conv (width 4) + bias + SiLU on xi half of xz
// ---------------------------------------------------------------
__global__ void __launch_bounds__(256) conv_silu_k(
    const float* __restrict__ cw, const float* __restrict__ cb)
{
    const int idx = blockIdx.x * 256 + threadIdx.x;   // over MROWS*DI
    const int d = idx & (DI - 1);
    const int m = idx >> 11;          // b*L + l
    const int l = m & (LSEQ - 1);

    float acc = cb[d];
#pragma unroll
    for (int j = 0; j < 4; j++) {
        const int ll = l - 3 + j;
        if (ll >= 0)
            acc = fmaf(cw[d * 4 + j], g_xz[(size_t)(m - 3 + j) * E2 + d], acc);
    }
    const float sg = 1.f / (1.f + __expf(-acc));
    g_xc[idx] = acc * sg;
}

// ---------------------------------------------------------------
// Selective scan. One thread per (b, d, s). 256 threads = 16 d x 16 s.
// Fused epilogue: y = (scan + D*u) * silu(z)
// ---------------------------------------------------------------
__global__ void __launch_bounds__(256) scan_k(
    const float* __restrict__ A_log, const float* __restrict__ Dp)
{
    const int s  = threadIdx.x & 15;
    const int dl = threadIdx.x >> 4;
    const int d  = blockIdx.x * 16 + dl;
    const int b  = blockIdx.y;

    const float As = -__expf(A_log[d * DS + s]);
    const float Dd = Dp[d];

    const float* dt_p = g_dt   + (size_t)b * LSEQ * DI + d;
    const float* u_p  = g_xc   + (size_t)b * LSEQ * DI + d;
    const float* bc_p = g_xdbl + (size_t)b * LSEQ * NX;
    const float* z_p  = g_xz   + (size_t)b * LSEQ * E2 + DI + d;
    float*       y_p  = g_yact + (size_t)b * LSEQ * DI + d;

    float h = 0.f;
    for (int l = 0; l < LSEQ; l++) {
        const float dt = __ldg(dt_p + (size_t)l * DI);
        const float u  = __ldg(u_p  + (size_t)l * DI);
        const float Bv = __ldg(bc_p + l * NX + DTR + s);
        const float Cv = __ldg(bc_p + l * NX + DTR + DS + s);

        const float dA = __expf(dt * As);
        h = fmaf(dA, h, dt * u * Bv);

        float y = h * Cv;
        y += __shfl_xor_sync(0xffffffffu, y, 8);
        y += __shfl_xor_sync(0xffffffffu, y, 4);
        y += __shfl_xor_sync(0xffffffffu, y, 2);
        y += __shfl_xor_sync(0xffffffffu, y, 1);

        if (s == 0) {
            const float zv = __ldg(z_p + (size_t)l * E2);
            const float sg = 1.f / (1.f + __expf(-zv));
            y_p[(size_t)l * DI] = (y + Dd * u) * (zv * sg);
        }
    }
}

// ---------------------------------------------------------------
// Residual add + LayerNorm. One block per row of 1024.
// ---------------------------------------------------------------
__global__ void __launch_bounds__(256) ln_k(
    const float* __restrict__ x,
    const float* __restrict__ g, const float* __restrict__ bb,
    float* __restrict__ out)
{
    const int r = blockIdx.x;
    const float* yp = g_yout + (size_t)r * DM;
    const float* xp = x      + (size_t)r * DM;

    float v[4];
    float sum = 0.f, sq = 0.f;
#pragma unroll
    for (int k = 0; k < 4; k++) {
        const int c = threadIdx.x + k * 256;
        const float t = yp[c] + xp[c];
        v[k] = t; sum += t; sq += t * t;
    }

    __shared__ float ssum[8], ssq[8];
#pragma unroll
    for (int o = 16; o; o >>= 1) {
        sum += __shfl_xor_sync(0xffffffffu, sum, o);
        sq  += __shfl_xor_sync(0xffffffffu, sq,  o);
    }
    const int w = threadIdx.x >> 5;
    if ((threadIdx.x & 31) == 0) { ssum[w] = sum; ssq[w] = sq; }
    __syncthreads();

    float ts = 0.f, tq = 0.f;
#pragma unroll
    for (int i = 0; i < 8; i++) { ts += ssum[i]; tq += ssq[i]; }

    const float mu  = ts * (1.f / DM);
    const float var = tq * (1.f / DM) - mu * mu;
    const float inv = rsqrtf(var + 1e-5f);

#pragma unroll
    for (int k = 0; k < 4; k++) {
        const int c = threadIdx.x + k * 256;
        out[(size_t)r * DM + c] = (v[k] - mu) * inv * g[c] + bb[c];
    }
}

// ---------------------------------------------------------------
extern "C" void kernel_launch(void* const* d_in, const int* in_sizes, int n_in,
                              void* d_out, int out_size)
{
    const float* x          = (const float*)d_in[0];
    const float* in_proj_w  = (const float*)d_in[1];
    const float* conv_w     = (const float*)d_in[2];
    const float* conv_b     = (const float*)d_in[3];
    const float* x_proj_w   = (const float*)d_in[4];
    const float* dt_proj_w  = (const float*)d_in[5];
    const float* dt_proj_b  = (const float*)d_in[6];
    const float* A_log      = (const float*)d_in[7];
    const float* Dp         = (const float*)d_in[8];
    const float* out_proj_w = (const float*)d_in[9];
    const float* ln_g       = (const float*)d_in[10];
    const float* ln_b       = (const float*)d_in[11];
    float* out = (float*)d_out;

    float *xz, *xc, *xdbl, *dt, *yact, *yout;
    cudaGetSymbolAddress((void**)&xz,   g_xz);
    cudaGetSymbolAddress((void**)&xc,   g_xc);
    cudaGetSymbolAddress((void**)&xdbl, g_xdbl);
    cudaGetSymbolAddress((void**)&dt,   g_dt);
    cudaGetSymbolAddress((void**)&yact, g_yact);
    cudaGetSymbolAddress((void**)&yout, g_yout);

    // 1) xz = x @ in_proj_w^T       (4096 x 4096 x 1024)
    sgemm_abt<0><<<dim3(E2 / 64, MROWS / 64), 256>>>(
        x, DM, in_proj_w, DM, xz, E2, E2, DM, nullptr);

    // 2) xc = silu(causal_conv(xi) + conv_b)
    conv_silu_k<<<(MROWS * DI) / 256, 256>>>(conv_w, conv_b);

    // 3) x_dbl = xc @ x_proj_w^T    (4096 x 96 x 2048)
    sgemm_abt<0><<<dim3((NX + 63) / 64, MROWS / 64), 256>>>(
        xc, DI, x_proj_w, DI, xdbl, NX, NX, DI, nullptr);

    // 4) dt = softplus(dt_r @ dt_proj_w^T + b)  (4096 x 2048 x 64)
    sgemm_abt<1><<<dim3(DI / 64, MROWS / 64), 256>>>(
        xdbl, NX, dt_proj_w, DTR, dt, DI, DI, DTR, dt_proj_b);

    // 5) selective scan + gating
    scan_k<<<dim3(DI / 16, BSZ), 256>>>(A_log, Dp);

    // 6) yout = yact @ out_proj_w^T (4096 x 1024 x 2048)
    sgemm_abt<0><<<dim3(DM / 64, MROWS / 64), 256>>>(
        yact, DI, out_proj_w, DI, yout, DM, DM, DI, nullptr);

    // 7) out = layernorm(yout + x)
    ln_k<<<MROWS, 256>>>(x, ln_g, ln_b, out);
}

// round 8
// speedup vs baseline: 1.0155x; 1.0006x over previous
#include <cuda_runtime.h>
#include <math.h>

// Problem constants (fixed by setup_inputs)
#define BSZ   2
#define LSEQ  2048
#define DM    1024
#define DI    2048          // d_inner
#define DS    16            // d_state
#define DTR   64            // dt_rank
#define NX    96            // dt_rank + 2*d_state
#define MROWS (BSZ*LSEQ)    // 4096
#define E2    (2*DI)        // 4096

// -------- scratch (device globals; no allocation allowed) --------
__device__ float g_xz  [(size_t)MROWS * E2];   // in_proj output (xi | z)
__device__ float g_xc  [(size_t)MROWS * DI];   // conv+silu output
__device__ float g_xdbl[(size_t)MROWS * NX];   // x_proj output (dt_r | B | C)
__device__ float g_dt  [(size_t)MROWS * DI];   // softplus(dt)
__device__ float g_yact[(size_t)MROWS * DI];   // scan out * silu(z)
__device__ float g_yout[(size_t)MROWS * DM];   // out_proj output

// ---------------------------------------------------------------
// Generic fp32 GEMM: C[M,N] = A[M,K] * B[N,K]^T  (both K-major)
// 64x64 tile, 256 threads, 4x4 micro-tile, K-tile 16.
// M must be a multiple of 64 (always 4096 here); N,K checked.
// EPI==1: v = softplus(v + bias[n])
// ---------------------------------------------------------------
template<int EPI>
__global__ void __launch_bounds__(256) sgemm_abt(
    const float* __restrict__ A, int lda,
    const float* __restrict__ Bm, int ldb,
    float* __restrict__ C, int ldc,
    int N, int K, const float* __restrict__ bias)
{
    __shared__ float As[16][68];   // 68 stride: keeps float4 alignment, cuts store conflicts
    __shared__ float Bs[16][68];

    const int tid = threadIdx.x;
    const int tx  = tid & 15;
    const int ty  = tid >> 4;
    const int m0  = blockIdx.y * 64;
    const int n0  = blockIdx.x * 64;

    const int lr = tid >> 2;        // 0..63 tile row for loads
    const int lk = (tid & 3) * 4;   // 0,4,8,12 k offset for loads

    float acc[4][4];
#pragma unroll
    for (int i = 0; i < 4; i++)
#pragma unroll
        for (int j = 0; j < 4; j++) acc[i][j] = 0.f;

    for (int k0 = 0; k0 < K; k0 += 16) {
        float4 av = *reinterpret_cast<const float4*>(
            A + (size_t)(m0 + lr) * lda + (k0 + lk));
        As[lk+0][lr] = av.x; As[lk+1][lr] = av.y;
        As[lk+2][lr] = av.z; As[lk+3][lr] = av.w;

        float4 bv = make_float4(0.f, 0.f, 0.f, 0.f);
        if (n0 + lr < N)
            bv = *reinterpret_cast<const float4*>(
                Bm + (size_t)(n0 + lr) * ldb + (k0 + lk));
        Bs[lk+0][lr] = bv.x; Bs[lk+1][lr] = bv.y;
        Bs[lk+2][lr] = bv.z; Bs[lk+3][lr] = bv.w;

        __syncthreads();
#pragma unroll
        for (int k = 0; k < 16; k++) {
            float4 a4 = *reinterpret_cast<const float4*>(&As[k][ty * 4]);
            float4 b4 = *reinterpret_cast<const float4*>(&Bs[k][tx * 4]);
            float a[4] = {a4.x, a4.y, a4.z, a4.w};
            float b[4] = {b4.x, b4.y, b4.z, b4.w};
#pragma unroll
            for (int i = 0; i < 4; i++)
#pragma unroll
                for (int j = 0; j < 4; j++)
                    acc[i][j] = fmaf(a[i], b[j], acc[i][j]);
        }
        __syncthreads();
    }

#pragma unroll
    for (int i = 0; i < 4; i++) {
        const int m = m0 + ty * 4 + i;
#pragma unroll
        for (int j = 0; j < 4; j++) {
            const int n = n0 + tx * 4 + j;
            if (n < N) {
                float v = acc[i][j];
                if (EPI == 1) {
                    v += bias[n];
                    v = (v > 20.f) ? v : log1pf(__expf(v));
                }
                C[(size_t)m * ldc + n] = v;
            }
        }
    }
}

// ---------------------------------------------------------------
// Causal depthwise conv (width 4) + bias + SiLU on xi half of xz
// ---------------------------------------------------------------
__global__ void __launch_bounds__(256) conv_silu_k(
    const float* __restrict__ cw, const float* __restrict__ cb)
{
    const int idx = blockIdx.x * 256 + threadIdx.x;   // over MROWS*DI
    const int d = idx & (DI - 1);
    const int m = idx >> 11;          // b*L + l
    const int l = m & (LSEQ - 1);

    float acc = cb[d];
#pragma unroll
    for (int j = 0; j < 4; j++) {
        const int ll = l - 3 + j;
        if (ll >= 0)
            acc = fmaf(cw[d * 4 + j], g_xz[(size_t)(m - 3 + j) * E2 + d], acc);
    }
    const float sg = 1.f / (1.f + __expf(-acc));
    g_xc[idx] = acc * sg;
}

// ---------------------------------------------------------------
// Selective scan. One thread per (b, d, s). 256 threads = 16 d x 16 s.
// Fused epilogue: y = (scan + D*u) * silu(z)
// ---------------------------------------------------------------
__global__ void __launch_bounds__(256) scan_k(
    const float* __restrict__ A_log, const float* __restrict__ Dp)
{
    const int s  = threadIdx.x & 15;
    const int dl = threadIdx.x >> 4;
    const int d  = blockIdx.x * 16 + dl;
    const int b  = blockIdx.y;

    const float As = -__expf(A_log[d * DS + s]);
    const float Dd = Dp[d];

    const float* dt_p = g_dt   + (size_t)b * LSEQ * DI + d;
    const float* u_p  = g_xc   + (size_t)b * LSEQ * DI + d;
    const float* bc_p = g_xdbl + (size_t)b * LSEQ * NX;
    const float* z_p  = g_xz   + (size_t)b * LSEQ * E2 + DI + d;
    float*       y_p  = g_yact + (size_t)b * LSEQ * DI + d;

    float h = 0.f;
    for (int l = 0; l < LSEQ; l++) {
        const float dt = __ldg(dt_p + (size_t)l * DI);
        const float u  = __ldg(u_p  + (size_t)l * DI);
        const float Bv = __ldg(bc_p + l * NX + DTR + s);
        const float Cv = __ldg(bc_p + l * NX + DTR + DS + s);

        const float dA = __expf(dt * As);
        h = fmaf(dA, h, dt * u * Bv);

        float y = h * Cv;
        y += __shfl_xor_sync(0xffffffffu, y, 8);
        y += __shfl_xor_sync(0xffffffffu, y, 4);
        y += __shfl_xor_sync(0xffffffffu, y, 2);
        y += __shfl_xor_sync(0xffffffffu, y, 1);

        if (s == 0) {
            const float zv = __ldg(z_p + (size_t)l * E2);
            const float sg = 1.f / (1.f + __expf(-zv));
            y_p[(size_t)l * DI] = (y + Dd * u) * (zv * sg);
        }
    }
}

// ---------------------------------------------------------------
// Residual add + LayerNorm. One block per row of 1024.
// ---------------------------------------------------------------
__global__ void __launch_bounds__(256) ln_k(
    const float* __restrict__ x,
    const float* __restrict__ g, const float* __restrict__ bb,
    float* __restrict__ out)
{
    const int r = blockIdx.x;
    const float* yp = g_yout + (size_t)r * DM;
    const float* xp = x      + (size_t)r * DM;

    float v[4];
    float sum = 0.f, sq = 0.f;
#pragma unroll
    for (int k = 0; k < 4; k++) {
        const int c = threadIdx.x + k * 256;
        const float t = yp[c] + xp[c];
        v[k] = t; sum += t; sq += t * t;
    }

    __shared__ float ssum[8], ssq[8];
#pragma unroll
    for (int o = 16; o; o >>= 1) {
        sum += __shfl_xor_sync(0xffffffffu, sum, o);
        sq  += __shfl_xor_sync(0xffffffffu, sq,  o);
    }
    const int w = threadIdx.x >> 5;
    if ((threadIdx.x & 31) == 0) { ssum[w] = sum; ssq[w] = sq; }
    __syncthreads();

    float ts = 0.f, tq = 0.f;
#pragma unroll
    for (int i = 0; i < 8; i++) { ts += ssum[i]; tq += ssq[i]; }

    const float mu  = ts * (1.f / DM);
    const float var = tq * (1.f / DM) - mu * mu;
    const float inv = rsqrtf(var + 1e-5f);

#pragma unroll
    for (int k = 0; k < 4; k++) {
        const int c = threadIdx.x + k * 256;
        out[(size_t)r * DM + c] = (v[k] - mu) * inv * g[c] + bb[c];
    }
}

// ---------------------------------------------------------------
extern "C" void kernel_launch(void* const* d_in, const int* in_sizes, int n_in,
                              void* d_out, int out_size)
{
    const float* x          = (const float*)d_in[0];
    const float* in_proj_w  = (const float*)d_in[1];
    const float* conv_w     = (const float*)d_in[2];
    const float* conv_b     = (const float*)d_in[3];
    const float* x_proj_w   = (const float*)d_in[4];
    const float* dt_proj_w  = (const float*)d_in[5];
    const float* dt_proj_b  = (const float*)d_in[6];
    const float* A_log      = (const float*)d_in[7];
    const float* Dp         = (const float*)d_in[8];
    const float* out_proj_w = (const float*)d_in[9];
    const float* ln_g       = (const float*)d_in[10];
    const float* ln_b       = (const float*)d_in[11];
    float* out = (float*)d_out;

    float *xz, *xc, *xdbl, *dt, *yact, *yout;
    cudaGetSymbolAddress((void**)&xz,   g_xz);
    cudaGetSymbolAddress((void**)&xc,   g_xc);
    cudaGetSymbolAddress((void**)&xdbl, g_xdbl);
    cudaGetSymbolAddress((void**)&dt,   g_dt);
    cudaGetSymbolAddress((void**)&yact, g_yact);
    cudaGetSymbolAddress((void**)&yout, g_yout);

    // 1) xz = x @ in_proj_w^T       (4096 x 4096 x 1024)
    sgemm_abt<0><<<dim3(E2 / 64, MROWS / 64), 256>>>(
        x, DM, in_proj_w, DM, xz, E2, E2, DM, nullptr);

    // 2) xc = silu(causal_conv(xi) + conv_b)
    conv_silu_k<<<(MROWS * DI) / 256, 256>>>(conv_w, conv_b);

    // 3) x_dbl = xc @ x_proj_w^T    (4096 x 96 x 2048)
    sgemm_abt<0><<<dim3((NX + 63) / 64, MROWS / 64), 256>>>(
        xc, DI, x_proj_w, DI, xdbl, NX, NX, DI, nullptr);

    // 4) dt = softplus(dt_r @ dt_proj_w^T + b)  (4096 x 2048 x 64)
    sgemm_abt<1><<<dim3(DI / 64, MROWS / 64), 256>>>(
        xdbl, NX, dt_proj_w, DTR, dt, DI, DI, DTR, dt_proj_b);

    // 5) selective scan + gating
    scan_k<<<dim3(DI / 16, BSZ), 256>>>(A_log, Dp);

    // 6) yout = yact @ out_proj_w^T (4096 x 1024 x 2048)
    sgemm_abt<0><<<dim3(DM / 64, MROWS / 64), 256>>>(
        yact, DI, out_proj_w, DI, yout, DM, DM, DI, nullptr);

    // 7) out = layernorm(yout + x)
    ln_k<<<MROWS, 256>>>(x, ln_g, ln_b, out);
}